// round 11
// baseline (speedup 1.0000x reference)
#include <cuda_runtime.h>
#include <cstdint>
#include <math.h>

// ---------------------------------------------------------------------------
// R22SDF fixed-point FFT, N=256 complex (512 real in), 16384 rows.
// out = float32[rows][257] = real part of the reference complex output.
// R11: = R10 (symmetry-halved post-combine, packed f32x2 quant, 9 twiddle
// loads) + __launch_bounds__(256,7) to lift occupancy 6->7 blocks/SM.
// Bit-exact vs reference.
// ---------------------------------------------------------------------------

#define MAX_ROWS 16384

// ===== compile-time quantized tables ========================================

struct alignas(8) C2 { float x, y; };

constexpr double PI_D = 3.141592653589793238462643383279502884;

constexpr double tsin(double x)
{
    double term = x, sum = x;
    for (int i = 1; i < 26; ++i) {
        term *= -(x * x) / double((2 * i) * (2 * i + 1));
        sum += term;
    }
    return sum;
}
constexpr double tcos(double x)
{
    double term = 1.0, sum = 1.0;
    for (int i = 1; i < 26; ++i) {
        term *= -(x * x) / double((2 * i - 1) * (2 * i));
        sum += term;
    }
    return sum;
}
// rint(float(v)*16)/16 — no ties occur (margin >= 5e-3), so half-away == RNE
constexpr float q16(double v)
{
    float s = (float)v * 16.0f;
    long r = (s >= 0.0f) ? (long)(s + 0.5f) : -(long)(-s + 0.5f);
    return (float)r * 0.0625f;
}
constexpr float q4(double v)
{
    float s = (float)v * 4.0f;
    long r = (s >= 0.0f) ? (long)(s + 0.5f) : -(long)(-s + 0.5f);
    return (float)r * 0.25f;
}
constexpr C2 wN(int nk, double Nv)
{
    double ang = -2.0 * PI_D * (double)nk / Nv;
    float cf = q16(tcos(ang)), sf = q16(tsin(ang));
    if (cf ==  1.0f) return {  1.0f, 0.0f};
    if (cf == -1.0f) return {-1.0f, 0.0f};
    if (sf ==  1.0f) return { 0.0f, 1.0f};
    if (sf == -1.0f) return { 0.0f,-1.0f};
    return {cf, sf};
}
constexpr int qm(int q) { return q == 1 ? 2 : (q == 2 ? 1 : 3); }

// ext2[k] = EXTRA[k] / 2 for k in [0,128]  (folds the 0.5 of x_even/x_odd)
struct Tables { C2 tw0[256]; C2 tw1[64]; C2 tw2[16]; C2 ext2[132]; };

constexpr Tables build_tables()
{
    Tables t{};
    for (int i = 0; i < 256; ++i) {
        int q = i >> 6, r = i & 63;
        t.tw0[i] = (q == 0) ? C2{1.0f, 0.0f} : wN(r * qm(q), 256.0);
    }
    for (int b = 0; b < 64; ++b) {
        int q = b >> 4, r = b & 15;
        t.tw1[b] = (q == 0) ? C2{1.0f, 0.0f} : wN(r * qm(q), 64.0);
    }
    for (int b = 0; b < 16; ++b) {
        int q = b >> 2, r = b & 3;
        t.tw2[b] = (q == 0) ? C2{1.0f, 0.0f} : wN(r * qm(q), 16.0);
    }
    for (int k = 0; k <= 128; ++k) {
        double ang = -PI_D * (double)k / 256.0;
        t.ext2[k] = C2{q4(tcos(ang)) * 0.5f, q4(tsin(ang)) * 0.5f};
    }
    return t;
}

__device__ constexpr Tables TBL = build_tables();

// ===== packed f32x2 helpers ===================================================

__device__ __forceinline__ float2 fadd2(float2 a, float2 b)
{
    float2 r;
    asm("{\n\t.reg .b64 pa, pb, pr;\n\t"
        "mov.b64 pa, {%2,%3};\n\tmov.b64 pb, {%4,%5};\n\t"
        "add.rn.f32x2 pr, pa, pb;\n\t"
        "mov.b64 {%0,%1}, pr;\n\t}"
        : "=f"(r.x), "=f"(r.y)
        : "f"(a.x), "f"(a.y), "f"(b.x), "f"(b.y));
    return r;
}
// round-toward-minus-infinity packed add (the magic-floor step)
__device__ __forceinline__ float2 fadd2_rm(float2 a, float2 b)
{
    float2 r;
    asm("{\n\t.reg .b64 pa, pb, pr;\n\t"
        "mov.b64 pa, {%2,%3};\n\tmov.b64 pb, {%4,%5};\n\t"
        "add.rm.f32x2 pr, pa, pb;\n\t"
        "mov.b64 {%0,%1}, pr;\n\t}"
        : "=f"(r.x), "=f"(r.y)
        : "f"(a.x), "f"(a.y), "f"(b.x), "f"(b.y));
    return r;
}
// r = a*b + c (componentwise)
__device__ __forceinline__ float2 ffma2(float2 a, float2 b, float2 c)
{
    float2 r;
    asm("{\n\t.reg .b64 pa, pb, pc, pr;\n\t"
        "mov.b64 pa, {%2,%3};\n\tmov.b64 pb, {%4,%5};\n\tmov.b64 pc, {%6,%7};\n\t"
        "fma.rn.f32x2 pr, pa, pb, pc;\n\t"
        "mov.b64 {%0,%1}, pr;\n\t}"
        : "=f"(r.x), "=f"(r.y)
        : "f"(a.x), "f"(a.y), "f"(b.x), "f"(b.y), "f"(c.x), "f"(c.y));
    return r;
}

// ===== math helpers ===========================================================

#define MAGIC   12582912.0f     // 2^23 + 2^22
#define MAGLO   12582784.0f     // MAGIC - 128
#define MAGHI   12583039.0f     // MAGIC + 127

// packed quant: t = rm(u + M); clamp t to [M-128, M+127] (monotonic, so this
// equals clamping u first); out = (t - M) * ratio, exact via fused fma.
__device__ __forceinline__ float2 qz2(float2 u, float ratio, float negMr)
{
    float2 t = fadd2_rm(u, make_float2(MAGIC, MAGIC));
    t.x = fminf(fmaxf(t.x, MAGLO), MAGHI);
    t.y = fminf(fmaxf(t.y, MAGLO), MAGHI);
    return ffma2(t, make_float2(ratio, ratio), make_float2(negMr, negMr));
}

__device__ __forceinline__ float2 cmulw(float2 a, float2 w)
{
    return make_float2(fmaf(a.x, w.x, -(a.y * w.y)),
                       fmaf(a.x, w.y,  (a.y * w.x)));
}

__device__ __forceinline__ float2 rot_mj(float2 a)   // a * (-i)
{
    return make_float2(a.y, -a.x);
}

__device__ __forceinline__ void bfly(float2& a, float2& b)
{
    float2 t = a;
    a = fadd2(t, b);                                        // t + b
    b = ffma2(b, make_float2(-1.0f, -1.0f), t);             // t - b
}

template <int BIT>
__device__ __forceinline__ void shfl_stage(float2 (&v)[8])
{
    float sg = (threadIdx.x & BIT) ? -1.0f : 1.0f;
    float2 sg2 = make_float2(sg, sg);
#pragma unroll
    for (int j = 0; j < 8; ++j) {
        float bx = __shfl_xor_sync(0xffffffffu, v[j].x, BIT);
        float by = __shfl_xor_sync(0xffffffffu, v[j].y, BIT);
        v[j] = ffma2(v[j], sg2, make_float2(bx, by));       // sign*v + partner
    }
}

__device__ __forceinline__ void quant8(float2 (&v)[8], float ratio, float negMr)
{
#pragma unroll
    for (int j = 0; j < 8; ++j) v[j] = qz2(v[j], ratio, negMr);
}

// ===== main kernel =============================================================

__global__ void __launch_bounds__(256, 7)
r22sdf_kernel(const float* __restrict__ xin, float* __restrict__ outf, int rows)
{
    __shared__ float2 sbuf[8][256];
    const int warp = threadIdx.x >> 5;
    const int lane = threadIdx.x & 31;
    const int row  = (blockIdx.x << 3) + warp;
    if (row >= rows) return;

    const float2* tw0 = reinterpret_cast<const float2*>(TBL.tw0);
    const float2* tw1 = reinterpret_cast<const float2*>(TBL.tw1);
    const float2* tw2 = reinterpret_cast<const float2*>(TBL.tw2);
    const float2* ex2 = reinterpret_cast<const float2*>(TBL.ext2);

    // ---- load: u = x * PRE_GAIN * s1 = x * 1024 (packed mul) -----------------
    const float2* xr = reinterpret_cast<const float2*>(xin) + (size_t)row * 256;
    float2 v[8];
    const float2 G = make_float2(1024.0f, 1024.0f);
    const float2 Z = make_float2(0.0f, 0.0f);
#pragma unroll
    for (int j = 0; j < 8; ++j)
        v[j] = ffma2(xr[lane + 32 * j], G, Z);

    // ---- stage 1: stride 128; trivial -i on i in [192,256); s=64 -------------
#pragma unroll
    for (int j = 0; j < 4; ++j) bfly(v[j], v[j + 4]);
    v[6] = rot_mj(v[6]);
    v[7] = rot_mj(v[7]);
    quant8(v, 1.0f, -MAGIC);                    // 64 -> 64

    // ---- stage 2: stride 64; TWIDDLE row 0; s=64 ------------------------------
    // TW0[i]: i>>6 = j>>1, so j=0,1 sit in the identity quarter -> skip cmul.
    bfly(v[0], v[2]); bfly(v[1], v[3]); bfly(v[4], v[6]); bfly(v[5], v[7]);
    {
        float2 wA = __ldg(&tw0[lane +  64]);
        float2 wB = __ldg(&tw0[lane +  96]);
        float2 wC = __ldg(&tw0[lane + 128]);
        float2 wD = __ldg(&tw0[lane + 160]);
        float2 wE = __ldg(&tw0[lane + 192]);
        float2 wF = __ldg(&tw0[lane + 224]);
        v[2] = cmulw(v[2], wA); v[3] = cmulw(v[3], wB);
        v[4] = cmulw(v[4], wC); v[5] = cmulw(v[5], wD);
        v[6] = cmulw(v[6], wE); v[7] = cmulw(v[7], wF);
    }
    quant8(v, 0.5f, -MAGIC * 0.5f);             // 64 -> 32

    // ---- stage 3: stride 32; trivial -i; s=32 ---------------------------------
    bfly(v[0], v[1]); bfly(v[2], v[3]); bfly(v[4], v[5]); bfly(v[6], v[7]);
    if (lane >= 16) {
        v[1] = rot_mj(v[1]); v[3] = rot_mj(v[3]);
        v[5] = rot_mj(v[5]); v[7] = rot_mj(v[7]);
    }
    quant8(v, 1.0f, -MAGIC);                    // 32 -> 32

    // ---- stage 4: stride 16 (shfl); TWIDDLE row 1 = f(i&63); s=32 -------------
    shfl_stage<16>(v);
    {
        float2 wa = __ldg(&tw1[lane]);          // j even
        float2 wb = __ldg(&tw1[lane + 32]);     // j odd
        v[0] = cmulw(v[0], wa); v[1] = cmulw(v[1], wb);
        v[2] = cmulw(v[2], wa); v[3] = cmulw(v[3], wb);
        v[4] = cmulw(v[4], wa); v[5] = cmulw(v[5], wb);
        v[6] = cmulw(v[6], wa); v[7] = cmulw(v[7], wb);
    }
    quant8(v, 0.25f, -MAGIC * 0.25f);           // 32 -> 8

    // ---- stage 5: stride 8 (shfl); trivial -i on (i&15)>=12; s=8 --------------
    shfl_stage<8>(v);
    if ((lane & 15) >= 12) {
#pragma unroll
        for (int j = 0; j < 8; ++j) v[j] = rot_mj(v[j]);
    }
    quant8(v, 1.0f, -MAGIC);                    // 8 -> 8

    // ---- stage 6: stride 4 (shfl); TWIDDLE row 2 = f(i&15); s=8 ---------------
    shfl_stage<4>(v);
    {
        float2 wc = __ldg(&tw2[lane & 15]);     // same for all j
#pragma unroll
        for (int j = 0; j < 8; ++j) v[j] = cmulw(v[j], wc);
    }
    quant8(v, 0.5f, -MAGIC * 0.5f);             // 8 -> 4

    // ---- stage 7: stride 2 (shfl); trivial -i on (i&3)==3; s=4 ----------------
    shfl_stage<2>(v);
    if ((lane & 3) == 3) {
#pragma unroll
        for (int j = 0; j < 8; ++j) v[j] = rot_mj(v[j]);
    }
    quant8(v, 1.0f, -MAGIC);                    // 4 -> 4

    // ---- stage 8: stride 1 (shfl); no twiddle, no quant ------------------------
    shfl_stage<1>(v);

    // ---- bit-reversed store to shared (XOR-swizzled, conflict-free) ------------
    float2* s = sbuf[warp];
    {
        const int r5 = (int)(__brev((unsigned)lane) >> 27);
        const int hi = r5 << 3;
        const int t  = r5 >> 2;
        static const int rev3[8] = {0, 4, 2, 6, 1, 5, 3, 7};
#pragma unroll
        for (int j = 0; j < 8; ++j)
            s[hi | (rev3[j] ^ t)] = v[j];
    }
    __syncwarp();

    // ---- post-combine via conjugate symmetry ------------------------------------
    // For pair (k, 256-k):  y(k)      = 0.5*A + ex2*B + ey2*C
    //                       y(256-k)  = A - y(k)
    // A = ax+bx, B = ay+by, C = ax-bx; out = clip(floor(y), -128,127)/64.
    float* orow = outf + (size_t)row * 257;
#pragma unroll
    for (int j = 0; j < 4; ++j) {
        int k   = lane + 32 * j;                 // 0..127
        int e1  = (lane ^ j) + 32 * j;           // k ^ (k>>5)
        int km  = (256 - k) & 255;
        int e2  = km ^ (km >> 5);
        float2 a = s[e1];
        float2 b = s[e2];
        float2 e = __ldg(&ex2[k]);
        float2 AB = fadd2(a, b);                 // (A, B)
        float  C  = a.x - b.x;
        float  y  = fmaf(e.y, C, fmaf(e.x, AB.y, 0.5f * AB.x));
        float  y2 = AB.x - y;                    // exact (dyadic, small)
        float2 q  = qz2(make_float2(y, y2), 1.0f/64.0f, -MAGIC * (1.0f/64.0f));
        orow[k]       = q.x;
        orow[256 - k] = q.y;
    }
    if (lane == 0) {     // k = 128: a = b = s[132], ex2=0, C=0 -> y = a.x
        float y = s[132].x;
        float t = __fadd_rd(y, MAGIC);
        t = fminf(fmaxf(t, MAGLO), MAGHI);
        orow[128] = fmaf(t, 1.0f/64.0f, -(MAGIC * (1.0f/64.0f)));
    }
}

// ===== launch ===================================================================

extern "C" void kernel_launch(void* const* d_in, const int* in_sizes, int n_in,
                              void* d_out, int out_size)
{
    const float* x = (const float*)d_in[0];

    int rows_in  = in_sizes[0] / 512;
    int rows_out = out_size / 257;
    int rows = rows_in < rows_out ? rows_in : rows_out;
    if (rows > MAX_ROWS) rows = MAX_ROWS;
    if (rows <= 0) return;

    r22sdf_kernel<<<(rows + 7) / 8, 256>>>(x, (float*)d_out, rows);
}

// round 12
// speedup vs baseline: 1.0507x; 1.0507x over previous
#include <cuda_runtime.h>
#include <cstdint>
#include <math.h>

// ---------------------------------------------------------------------------
// R22SDF fixed-point FFT, N=256 complex (512 real in), 16384 rows.
// out = float32[rows][257] = real part of the reference complex output.
// R12: mid-pipeline smem transpose after stage 5 -> stages 6/7/8 intra-thread
// (SHFL 80 -> 32). Same swizzle proven conflict-free for all patterns.
// Bit-exact vs reference.
// ---------------------------------------------------------------------------

#define MAX_ROWS 16384

// ===== compile-time quantized tables ========================================

struct alignas(8) C2 { float x, y; };

constexpr double PI_D = 3.141592653589793238462643383279502884;

constexpr double tsin(double x)
{
    double term = x, sum = x;
    for (int i = 1; i < 26; ++i) {
        term *= -(x * x) / double((2 * i) * (2 * i + 1));
        sum += term;
    }
    return sum;
}
constexpr double tcos(double x)
{
    double term = 1.0, sum = 1.0;
    for (int i = 1; i < 26; ++i) {
        term *= -(x * x) / double((2 * i - 1) * (2 * i));
        sum += term;
    }
    return sum;
}
// rint(float(v)*16)/16 — no ties occur (margin >= 5e-3), so half-away == RNE
constexpr float q16(double v)
{
    float s = (float)v * 16.0f;
    long r = (s >= 0.0f) ? (long)(s + 0.5f) : -(long)(-s + 0.5f);
    return (float)r * 0.0625f;
}
constexpr float q4(double v)
{
    float s = (float)v * 4.0f;
    long r = (s >= 0.0f) ? (long)(s + 0.5f) : -(long)(-s + 0.5f);
    return (float)r * 0.25f;
}
constexpr C2 wN(int nk, double Nv)
{
    double ang = -2.0 * PI_D * (double)nk / Nv;
    float cf = q16(tcos(ang)), sf = q16(tsin(ang));
    if (cf ==  1.0f) return {  1.0f, 0.0f};
    if (cf == -1.0f) return {-1.0f, 0.0f};
    if (sf ==  1.0f) return { 0.0f, 1.0f};
    if (sf == -1.0f) return { 0.0f,-1.0f};
    return {cf, sf};
}
constexpr int qm(int q) { return q == 1 ? 2 : (q == 2 ? 1 : 3); }

// ext2[k] = EXTRA[k] / 2 for k in [0,128]  (folds the 0.5 of x_even/x_odd)
struct alignas(16) Tables { C2 tw0[256]; C2 tw1[64]; C2 tw2[16]; C2 ext2[132]; };

constexpr Tables build_tables()
{
    Tables t{};
    for (int i = 0; i < 256; ++i) {
        int q = i >> 6, r = i & 63;
        t.tw0[i] = (q == 0) ? C2{1.0f, 0.0f} : wN(r * qm(q), 256.0);
    }
    for (int b = 0; b < 64; ++b) {
        int q = b >> 4, r = b & 15;
        t.tw1[b] = (q == 0) ? C2{1.0f, 0.0f} : wN(r * qm(q), 64.0);
    }
    for (int b = 0; b < 16; ++b) {
        int q = b >> 2, r = b & 3;
        t.tw2[b] = (q == 0) ? C2{1.0f, 0.0f} : wN(r * qm(q), 16.0);
    }
    for (int k = 0; k <= 128; ++k) {
        double ang = -PI_D * (double)k / 256.0;
        t.ext2[k] = C2{q4(tcos(ang)) * 0.5f, q4(tsin(ang)) * 0.5f};
    }
    return t;
}

__device__ constexpr Tables TBL = build_tables();

// ===== packed f32x2 helpers ===================================================

__device__ __forceinline__ float2 fadd2(float2 a, float2 b)
{
    float2 r;
    asm("{\n\t.reg .b64 pa, pb, pr;\n\t"
        "mov.b64 pa, {%2,%3};\n\tmov.b64 pb, {%4,%5};\n\t"
        "add.rn.f32x2 pr, pa, pb;\n\t"
        "mov.b64 {%0,%1}, pr;\n\t}"
        : "=f"(r.x), "=f"(r.y)
        : "f"(a.x), "f"(a.y), "f"(b.x), "f"(b.y));
    return r;
}
// round-toward-minus-infinity packed add (the magic-floor step)
__device__ __forceinline__ float2 fadd2_rm(float2 a, float2 b)
{
    float2 r;
    asm("{\n\t.reg .b64 pa, pb, pr;\n\t"
        "mov.b64 pa, {%2,%3};\n\tmov.b64 pb, {%4,%5};\n\t"
        "add.rm.f32x2 pr, pa, pb;\n\t"
        "mov.b64 {%0,%1}, pr;\n\t}"
        : "=f"(r.x), "=f"(r.y)
        : "f"(a.x), "f"(a.y), "f"(b.x), "f"(b.y));
    return r;
}
// r = a*b + c (componentwise)
__device__ __forceinline__ float2 ffma2(float2 a, float2 b, float2 c)
{
    float2 r;
    asm("{\n\t.reg .b64 pa, pb, pc, pr;\n\t"
        "mov.b64 pa, {%2,%3};\n\tmov.b64 pb, {%4,%5};\n\tmov.b64 pc, {%6,%7};\n\t"
        "fma.rn.f32x2 pr, pa, pb, pc;\n\t"
        "mov.b64 {%0,%1}, pr;\n\t}"
        : "=f"(r.x), "=f"(r.y)
        : "f"(a.x), "f"(a.y), "f"(b.x), "f"(b.y), "f"(c.x), "f"(c.y));
    return r;
}

// ===== math helpers ===========================================================

#define MAGIC   12582912.0f     // 2^23 + 2^22
#define MAGLO   12582784.0f     // MAGIC - 128
#define MAGHI   12583039.0f     // MAGIC + 127

// packed quant: t = rm(u + M); clamp t to [M-128, M+127] (monotonic, so this
// equals clamping u first); out = (t - M) * ratio, exact via fused fma.
__device__ __forceinline__ float2 qz2(float2 u, float ratio, float negMr)
{
    float2 t = fadd2_rm(u, make_float2(MAGIC, MAGIC));
    t.x = fminf(fmaxf(t.x, MAGLO), MAGHI);
    t.y = fminf(fmaxf(t.y, MAGLO), MAGHI);
    return ffma2(t, make_float2(ratio, ratio), make_float2(negMr, negMr));
}

__device__ __forceinline__ float2 cmulw(float2 a, float2 w)
{
    return make_float2(fmaf(a.x, w.x, -(a.y * w.y)),
                       fmaf(a.x, w.y,  (a.y * w.x)));
}

__device__ __forceinline__ float2 rot_mj(float2 a)   // a * (-i)
{
    return make_float2(a.y, -a.x);
}

__device__ __forceinline__ void bfly(float2& a, float2& b)
{
    float2 t = a;
    a = fadd2(t, b);                                        // t + b
    b = ffma2(b, make_float2(-1.0f, -1.0f), t);             // t - b
}

template <int BIT>
__device__ __forceinline__ void shfl_stage(float2 (&v)[8])
{
    float sg = (threadIdx.x & BIT) ? -1.0f : 1.0f;
    float2 sg2 = make_float2(sg, sg);
#pragma unroll
    for (int j = 0; j < 8; ++j) {
        float bx = __shfl_xor_sync(0xffffffffu, v[j].x, BIT);
        float by = __shfl_xor_sync(0xffffffffu, v[j].y, BIT);
        v[j] = ffma2(v[j], sg2, make_float2(bx, by));       // sign*v + partner
    }
}

__device__ __forceinline__ void quant8(float2 (&v)[8], float ratio, float negMr)
{
#pragma unroll
    for (int j = 0; j < 8; ++j) v[j] = qz2(v[j], ratio, negMr);
}

// ===== main kernel =============================================================

__global__ void __launch_bounds__(256)
r22sdf_kernel(const float* __restrict__ xin, float* __restrict__ outf, int rows)
{
    __shared__ float2 sbuf[8][256];
    const int warp = threadIdx.x >> 5;
    const int lane = threadIdx.x & 31;
    const int row  = (blockIdx.x << 3) + warp;
    if (row >= rows) return;

    const float2* tw0 = reinterpret_cast<const float2*>(TBL.tw0);
    const float2* tw1 = reinterpret_cast<const float2*>(TBL.tw1);
    const float4* tw2v = reinterpret_cast<const float4*>(TBL.tw2);
    const float2* ex2 = reinterpret_cast<const float2*>(TBL.ext2);

    // ---- load: u = x * PRE_GAIN * s1 = x * 1024 (packed mul) -----------------
    const float2* xr = reinterpret_cast<const float2*>(xin) + (size_t)row * 256;
    float2 v[8];
    const float2 G = make_float2(1024.0f, 1024.0f);
    const float2 Z = make_float2(0.0f, 0.0f);
#pragma unroll
    for (int j = 0; j < 8; ++j)
        v[j] = ffma2(xr[lane + 32 * j], G, Z);

    // ---- stage 1: stride 128; trivial -i on i in [192,256); s=64 -------------
#pragma unroll
    for (int j = 0; j < 4; ++j) bfly(v[j], v[j + 4]);
    v[6] = rot_mj(v[6]);
    v[7] = rot_mj(v[7]);
    quant8(v, 1.0f, -MAGIC);                    // 64 -> 64

    // ---- stage 2: stride 64; TWIDDLE row 0; s=64 ------------------------------
    // TW0[i]: i>>6 = j>>1, so j=0,1 sit in the identity quarter -> skip cmul.
    bfly(v[0], v[2]); bfly(v[1], v[3]); bfly(v[4], v[6]); bfly(v[5], v[7]);
    {
        float2 wA = __ldg(&tw0[lane +  64]);
        float2 wB = __ldg(&tw0[lane +  96]);
        float2 wC = __ldg(&tw0[lane + 128]);
        float2 wD = __ldg(&tw0[lane + 160]);
        float2 wE = __ldg(&tw0[lane + 192]);
        float2 wF = __ldg(&tw0[lane + 224]);
        v[2] = cmulw(v[2], wA); v[3] = cmulw(v[3], wB);
        v[4] = cmulw(v[4], wC); v[5] = cmulw(v[5], wD);
        v[6] = cmulw(v[6], wE); v[7] = cmulw(v[7], wF);
    }
    quant8(v, 0.5f, -MAGIC * 0.5f);             // 64 -> 32

    // ---- stage 3: stride 32; trivial -i; s=32 ---------------------------------
    bfly(v[0], v[1]); bfly(v[2], v[3]); bfly(v[4], v[5]); bfly(v[6], v[7]);
    if (lane >= 16) {
        v[1] = rot_mj(v[1]); v[3] = rot_mj(v[3]);
        v[5] = rot_mj(v[5]); v[7] = rot_mj(v[7]);
    }
    quant8(v, 1.0f, -MAGIC);                    // 32 -> 32

    // ---- stage 4: stride 16 (shfl); TWIDDLE row 1 = f(i&63); s=32 -------------
    shfl_stage<16>(v);
    {
        float2 wa = __ldg(&tw1[lane]);          // j even
        float2 wb = __ldg(&tw1[lane + 32]);     // j odd
        v[0] = cmulw(v[0], wa); v[1] = cmulw(v[1], wb);
        v[2] = cmulw(v[2], wa); v[3] = cmulw(v[3], wb);
        v[4] = cmulw(v[4], wa); v[5] = cmulw(v[5], wb);
        v[6] = cmulw(v[6], wa); v[7] = cmulw(v[7], wb);
    }
    quant8(v, 0.25f, -MAGIC * 0.25f);           // 32 -> 8

    // ---- stage 5: stride 8 (shfl); trivial -i on (i&15)>=12; s=8 --------------
    shfl_stage<8>(v);
    if ((lane & 15) >= 12) {
#pragma unroll
        for (int j = 0; j < 8; ++j) v[j] = rot_mj(v[j]);
    }
    quant8(v, 1.0f, -MAGIC);                    // 8 -> 8

    // ---- transpose: layout A (i = lane+32j) -> layout B (i = 8*lane+e) --------
    // swizzle phys(i) = i ^ (i>>5); conflict-free for both patterns.
    float2* s = sbuf[warp];
#pragma unroll
    for (int j = 0; j < 8; ++j)
        s[(lane ^ j) + 32 * j] = v[j];
    __syncwarp();
    float2 w[8];
    {
        const int base = 8 * lane;
        const int q = lane >> 2;
#pragma unroll
        for (int e = 0; e < 8; ++e)
            w[e] = s[base + (e ^ q)];
    }

    // ---- stage 6: stride 4 (intra); TWIDDLE row 2 = f(i&15); s=8 ---------------
    bfly(w[0], w[4]); bfly(w[1], w[5]); bfly(w[2], w[6]); bfly(w[3], w[7]);
    {
        // TW2[(8*lane+e) & 15] = TW2[8*(lane&1) + e], e = 0..7 -> 4 float4 loads
        const int b4 = 4 * (lane & 1);
        float4 t0 = __ldg(&tw2v[b4 + 0]);
        float4 t1 = __ldg(&tw2v[b4 + 1]);
        float4 t2 = __ldg(&tw2v[b4 + 2]);
        float4 t3 = __ldg(&tw2v[b4 + 3]);
        w[0] = cmulw(w[0], make_float2(t0.x, t0.y));
        w[1] = cmulw(w[1], make_float2(t0.z, t0.w));
        w[2] = cmulw(w[2], make_float2(t1.x, t1.y));
        w[3] = cmulw(w[3], make_float2(t1.z, t1.w));
        w[4] = cmulw(w[4], make_float2(t2.x, t2.y));
        w[5] = cmulw(w[5], make_float2(t2.z, t2.w));
        w[6] = cmulw(w[6], make_float2(t3.x, t3.y));
        w[7] = cmulw(w[7], make_float2(t3.z, t3.w));
    }
    quant8(w, 0.5f, -MAGIC * 0.5f);             // 8 -> 4

    // ---- stage 7: stride 2 (intra); trivial -i on e in {3,7} (uniform); s=4 ----
    bfly(w[0], w[2]); bfly(w[1], w[3]); bfly(w[4], w[6]); bfly(w[5], w[7]);
    w[3] = rot_mj(w[3]);
    w[7] = rot_mj(w[7]);
    quant8(w, 1.0f, -MAGIC);                    // 4 -> 4

    // ---- stage 8: stride 1 (intra); no twiddle, no quant ------------------------
    bfly(w[0], w[1]); bfly(w[2], w[3]); bfly(w[4], w[5]); bfly(w[6], w[7]);

    // ---- bit-reversed store: i = 8*lane+e -> p = 32*rev3(e) + rev5(lane) --------
    __syncwarp();   // all transpose reads done before overwriting
    {
        const int r5 = (int)(__brev((unsigned)lane) >> 27);
        static const int rev3[8] = {0, 4, 2, 6, 1, 5, 3, 7};
#pragma unroll
        for (int e = 0; e < 8; ++e)
            s[(r5 ^ rev3[e]) + 32 * rev3[e]] = w[e];   // phys = p ^ (p>>5)
    }
    __syncwarp();

    // ---- post-combine via conjugate symmetry ------------------------------------
    // For pair (k, 256-k):  y(k)      = 0.5*A + ex2*B + ey2*C
    //                       y(256-k)  = A - y(k)
    // A = ax+bx, B = ay+by, C = ax-bx; out = clip(floor(y), -128,127)/64.
    float* orow = outf + (size_t)row * 257;
#pragma unroll
    for (int j = 0; j < 4; ++j) {
        int k   = lane + 32 * j;                 // 0..127
        int e1  = (lane ^ j) + 32 * j;           // k ^ (k>>5)
        int km  = (256 - k) & 255;
        int e2  = km ^ (km >> 5);
        float2 a = s[e1];
        float2 b = s[e2];
        float2 e = __ldg(&ex2[k]);
        float2 AB = fadd2(a, b);                 // (A, B)
        float  C  = a.x - b.x;
        float  y  = fmaf(e.y, C, fmaf(e.x, AB.y, 0.5f * AB.x));
        float  y2 = AB.x - y;                    // exact (dyadic, small)
        float2 q  = qz2(make_float2(y, y2), 1.0f/64.0f, -MAGIC * (1.0f/64.0f));
        orow[k]       = q.x;
        orow[256 - k] = q.y;
    }
    if (lane == 0) {     // k = 128: a = b = s[132], ex2=0, C=0 -> y = a.x
        float y = s[132].x;
        float t = __fadd_rd(y, MAGIC);
        t = fminf(fmaxf(t, MAGLO), MAGHI);
        orow[128] = fmaf(t, 1.0f/64.0f, -(MAGIC * (1.0f/64.0f)));
    }
}

// ===== launch ===================================================================

extern "C" void kernel_launch(void* const* d_in, const int* in_sizes, int n_in,
                              void* d_out, int out_size)
{
    const float* x = (const float*)d_in[0];

    int rows_in  = in_sizes[0] / 512;
    int rows_out = out_size / 257;
    int rows = rows_in < rows_out ? rows_in : rows_out;
    if (rows > MAX_ROWS) rows = MAX_ROWS;
    if (rows <= 0) return;

    r22sdf_kernel<<<(rows + 7) / 8, 256>>>(x, (float*)d_out, rows);
}